// round 12
// baseline (speedup 1.0000x reference)
#include <cuda_runtime.h>
#include <cstdint>

#define NN 100000
#define EE 1600000
#define IN_DIM 128
#define OUT_DIM 64
#define TT 8
#define EPS_ 1e-7f
#define CSR_CAP (EE + 16 * NN)
#define NB 48                     // nodes per GEMM block (4 warps x 12)
#define COSH1 1.5430806348152437f
#define NCHUNK 4
#define CHUNK (NN / NCHUNK)       // 25000

typedef unsigned long long ull;

// ---------------- scratch ----------------
__device__ int   g_cnt[NN];
__device__ int   g_off[NN];
__device__ int   g_cur[NN];
__device__ int   g_csr[CSR_CAP];                       // padding slots = NN (dummy)
__device__ float g_hs[(size_t)(NN + 1) * OUT_DIM];     // dinv[n]*(x@W); row NN zeros
__device__ float g_h[(size_t)NN * OUT_DIM];            // aggregated + bias
__device__ int   g_cursor;

__device__ __forceinline__ void pfma(ull& acc, ull x, ull w) {
    asm("fma.rn.f32x2 %0, %1, %2, %0;" : "+l"(acc) : "l"(x), "l"(w));
}

// ---------------- kernels ----------------

__global__ void init_kernel() {
    int i = blockIdx.x * blockDim.x + threadIdx.x;
    if (i < NN) g_cnt[i] = 0;
    if (i < OUT_DIM) g_hs[(size_t)NN * OUT_DIM + i] = 0.0f;
    if (i == 0) g_cursor = 0;
}

__global__ void hist_kernel(const int* __restrict__ dst) {
    int e = blockIdx.x * blockDim.x + threadIdx.x;
    if (e >= EE) return;
    atomicAdd(&g_cnt[dst[e]], 1);
}

// per-block scan + global bump allocator; pads buckets to multiple of 16
__global__ void offsets_kernel() {
    int i = blockIdx.x * 1024 + threadIdx.x;
    int lane = threadIdx.x & 31, wid = threadIdx.x >> 5;
    int c = (i < NN) ? g_cnt[i] : 0;
    int pc = (c + 15) & ~15;

    int v = pc;
#pragma unroll
    for (int o = 1; o < 32; o <<= 1) {
        int t = __shfl_up_sync(0xffffffffu, v, o);
        if (lane >= o) v += t;
    }
    __shared__ int wsum[32];
    __shared__ int base;
    if (lane == 31) wsum[wid] = v;
    __syncthreads();
    if (wid == 0) {
        int w = wsum[lane];
#pragma unroll
        for (int o = 1; o < 32; o <<= 1) {
            int t = __shfl_up_sync(0xffffffffu, w, o);
            if (lane >= o) w += t;
        }
        wsum[lane] = w;
    }
    __syncthreads();
    int incl = v + ((wid > 0) ? wsum[wid - 1] : 0);
    if (threadIdx.x == 1023) base = atomicAdd(&g_cursor, incl);
    __syncthreads();
    if (i < NN) {
        int off = base + incl - pc;
        g_off[i] = off;
        g_cur[i] = off;
        for (int j = c; j < pc; j++) g_csr[off + j] = NN;   // dummy padding
    }
}

// h_s = dinv * (x @ W): 12 nodes per warp, 4 warps/block (NB=48); dinv inline
__global__ void __launch_bounds__(128) gemm_kernel(const float* __restrict__ x,
                                                   const float* __restrict__ W) {
    extern __shared__ ull sm[];
    ull* Wq = sm;            // [32 kk2][64 j][2] pairs-of-pairs, 32 KB
    ull* xs = sm + 4096;     // [48 node][64 kk], 24 KB

    int tid = threadIdx.x;
    int n0 = blockIdx.x * NB;

    for (int i = tid; i < 64 * 64; i += 128) {
        int kk = i >> 6, j = i & 63;
        int kk2 = kk >> 1, lo = kk & 1;
        float w0 = W[(2 * kk) * OUT_DIM + j];
        float w1 = W[(2 * kk + 1) * OUT_DIM + j];
        ull p; asm("mov.b64 %0, {%1, %2};" : "=l"(p) : "f"(w0), "f"(w1));
        Wq[kk2 * 128 + j * 2 + lo] = p;
    }
    const ull* x2 = (const ull*)x;
    for (int i = tid; i < NB * 64; i += 128) {
        int node = i >> 6, kk = i & 63;
        int gn = n0 + node;
        xs[i] = (gn < NN) ? x2[(size_t)gn * 64 + kk] : 0ull;
    }
    __syncthreads();

    int wid = tid >> 5, lane = tid & 31;
    const ull* xw = xs + wid * 12 * 64;

    ull a0[12], a1[12];
#pragma unroll
    for (int n = 0; n < 12; n++) { a0[n] = 0ull; a1[n] = 0ull; }

#pragma unroll 2
    for (int kk2 = 0; kk2 < 32; kk2++) {
        ulonglong2 wa = *(const ulonglong2*)(Wq + kk2 * 128 + 2 * lane);
        ulonglong2 wb = *(const ulonglong2*)(Wq + kk2 * 128 + 2 * (lane + 32));
#pragma unroll
        for (int n = 0; n < 12; n++) {
            ulonglong2 xv = *(const ulonglong2*)(xw + n * 64 + 2 * kk2);
            pfma(a0[n], xv.x, wa.x);
            pfma(a1[n], xv.x, wb.x);
            pfma(a0[n], xv.y, wa.y);
            pfma(a1[n], xv.y, wb.y);
        }
    }

#pragma unroll
    for (int n = 0; n < 12; n++) {
        int gn = n0 + wid * 12 + n;
        if (gn >= NN) break;
        float lo, hi, lo1, hi1;
        asm("mov.b64 {%0, %1}, %2;" : "=f"(lo), "=f"(hi) : "l"(a0[n]));
        asm("mov.b64 {%0, %1}, %2;" : "=f"(lo1), "=f"(hi1) : "l"(a1[n]));
        float di = rsqrtf((float)(g_cnt[gn] + 1));
        g_hs[(size_t)gn * OUT_DIM + lane]      = (lo + hi) * di;
        g_hs[(size_t)gn * OUT_DIM + lane + 32] = (lo1 + hi1) * di;
    }
}

__global__ void bucket_kernel(const int* __restrict__ ei) {
    int e = blockIdx.x * blockDim.x + threadIdx.x;
    if (e >= EE) return;
    int s = ei[e];
    int d = ei[EE + e];
    int pos = atomicAdd(&g_cur[d], 1);
    g_csr[pos] = s;
}

// warp per node: gather in-edges (16 in flight), h = dinv[d]*sum + bias
__global__ void gather_kernel(const float* __restrict__ b, int n_base) {
    int warp = (blockIdx.x * blockDim.x + threadIdx.x) >> 5;
    int lane = threadIdx.x & 31;
    if (warp >= CHUNK) return;
    const int n = n_base + warp;

    int cnt = g_cnt[n];
    int off = g_off[n];
    int mp = (cnt + 15) & ~15;
    const float2* hs2 = (const float2*)g_hs;

    float2 acc = hs2[(size_t)n * 32 + lane];   // self loop (prescaled by dinv[n])

    for (int i = 0; i < mp; i += 16) {
        int4 a = __ldg((const int4*)(g_csr + off + i));
        int4 c = __ldg((const int4*)(g_csr + off + i + 4));
        int4 d4 = __ldg((const int4*)(g_csr + off + i + 8));
        int4 e4 = __ldg((const int4*)(g_csr + off + i + 12));
        float2 v0 = hs2[(size_t)a.x * 32 + lane];
        float2 v1 = hs2[(size_t)a.y * 32 + lane];
        float2 v2 = hs2[(size_t)a.z * 32 + lane];
        float2 v3 = hs2[(size_t)a.w * 32 + lane];
        float2 v4 = hs2[(size_t)c.x * 32 + lane];
        float2 v5 = hs2[(size_t)c.y * 32 + lane];
        float2 v6 = hs2[(size_t)c.z * 32 + lane];
        float2 v7 = hs2[(size_t)c.w * 32 + lane];
        float2 v8 = hs2[(size_t)d4.x * 32 + lane];
        float2 v9 = hs2[(size_t)d4.y * 32 + lane];
        float2 va = hs2[(size_t)d4.z * 32 + lane];
        float2 vb = hs2[(size_t)d4.w * 32 + lane];
        float2 vc = hs2[(size_t)e4.x * 32 + lane];
        float2 vd = hs2[(size_t)e4.y * 32 + lane];
        float2 ve = hs2[(size_t)e4.z * 32 + lane];
        float2 vf = hs2[(size_t)e4.w * 32 + lane];
        acc.x += (((v0.x + v1.x) + (v2.x + v3.x)) + ((v4.x + v5.x) + (v6.x + v7.x)))
               + (((v8.x + v9.x) + (va.x + vb.x)) + ((vc.x + vd.x) + (ve.x + vf.x)));
        acc.y += (((v0.y + v1.y) + (v2.y + v3.y)) + ((v4.y + v5.y) + (v6.y + v7.y)))
               + (((v8.y + v9.y) + (va.y + vb.y)) + ((vc.y + vd.y) + (ve.y + vf.y)));
    }

    float di = rsqrtf((float)(cnt + 1));
    float2 bb = ((const float2*)b)[lane];
    float2 out = make_float2(fmaf(di, acc.x, bb.x), fmaf(di, acc.y, bb.y));
    ((float2*)g_h)[(size_t)n * 32 + lane] = out;
}

// quad per node (4 lanes, 16 comps each): 8-step Lorentz recurrence
__global__ void __launch_bounds__(256) time_kernel(float* __restrict__ o_out,
                                                   float* __restrict__ z_out,
                                                   int n_base) {
    int gid = blockIdx.x * 256 + threadIdx.x;
    int ln = gid >> 2;
    if (ln >= CHUNK) return;
    int node = n_base + ln;
    int q = gid & 3;

    const float4* hp = (const float4*)(g_h + (size_t)node * OUT_DIM + q * 16);
    float4 h[4], z[4], u[4];
#pragma unroll
    for (int j = 0; j < 4; j++) h[j] = hp[j];
#pragma unroll
    for (int j = 0; j < 4; j++) z[j] = make_float4(0.f, 0.f, 0.f, 0.f);
    if (q == 0) z[0].x = 1.0f;

#pragma unroll
    for (int t = 0; t < TT; t++) {
        float p = 0.f;
#pragma unroll
        for (int j = 0; j < 4; j++) {
            p = fmaf(z[j].x, h[j].x, p); p = fmaf(z[j].y, h[j].y, p);
            p = fmaf(z[j].z, h[j].z, p); p = fmaf(z[j].w, h[j].w, p);
        }
        p += __shfl_xor_sync(0xffffffffu, p, 1);
        p += __shfl_xor_sync(0xffffffffu, p, 2);
        float t00 = __shfl_sync(0xffffffffu, z[0].x * h[0].x, 0, 4);
        float lz = p - 2.0f * t00;

#pragma unroll
        for (int j = 0; j < 4; j++) {
            u[j].x = fmaf(lz, z[j].x, h[j].x);
            u[j].y = fmaf(lz, z[j].y, h[j].y);
            u[j].z = fmaf(lz, z[j].z, h[j].z);
            u[j].w = fmaf(lz, z[j].w, h[j].w);
        }
        float qq = 0.f;
#pragma unroll
        for (int j = 0; j < 4; j++) {
            qq = fmaf(u[j].x, u[j].x, qq); qq = fmaf(u[j].y, u[j].y, qq);
            qq = fmaf(u[j].z, u[j].z, qq); qq = fmaf(u[j].w, u[j].w, qq);
        }
        qq += __shfl_xor_sync(0xffffffffu, qq, 1);
        qq += __shfl_xor_sync(0xffffffffu, qq, 2);
        float u0 = __shfl_sync(0xffffffffu, u[0].x, 0, 4);
        float uu = qq - 2.0f * u0 * u0;

        float un2 = fmaxf(uu, EPS_);
        float un = sqrtf(un2);
        float ch, sh_;
        if (un < 0.03f) {                       // series (avoids cancellation)
            ch = fmaf(un2, 0.5f, 1.0f);
            sh_ = fmaf(un2, 0.16666667f, 1.0f);
        } else {
            float e = __expf(un);
            float ei = __fdividef(1.0f, e);
            ch = 0.5f * (e + ei);
            sh_ = __fdividef(0.5f * (e - ei), un);
        }
#pragma unroll
        for (int j = 0; j < 4; j++) {
            z[j].x = fmaf(ch, z[j].x, sh_ * u[j].x);
            z[j].y = fmaf(ch, z[j].y, sh_ * u[j].y);
            z[j].z = fmaf(ch, z[j].z, sh_ * u[j].z);
            z[j].w = fmaf(ch, z[j].w, sh_ * u[j].w);
        }

        // spike: arccosh(z0) >= 1  <=>  z0 >= cosh(1)
        float z0b = __shfl_sync(0xffffffffu, z[0].x, 0, 4);
        bool spike = (z0b >= COSH1);
        if (spike) {
#pragma unroll
            for (int j = 0; j < 4; j++) z[j] = make_float4(0.f, 0.f, 0.f, 0.f);
            if (q == 0) z[0].x = 1.0f;
        }

        if (q == 0) o_out[(size_t)t * NN + node] = spike ? 1.0f : 0.0f;
        float4* zp = (float4*)(z_out + (size_t)t * NN * OUT_DIM + (size_t)node * OUT_DIM + q * 16);
#pragma unroll
        for (int j = 0; j < 4; j++) zp[j] = z[j];
    }
}

// ---------------- launch ----------------
extern "C" void kernel_launch(void* const* d_in, const int* in_sizes, int n_in,
                              void* d_out, int out_size) {
    const float* x  = (const float*)d_in[0];
    const int*   ei = (const int*)d_in[1];
    const float* W  = (const float*)d_in[2];
    const float* b  = (const float*)d_in[3];

    float* o_out = (float*)d_out;              // [T, N]
    float* z_out = o_out + (size_t)TT * NN;    // [T, N, 64]

    static cudaStream_t s1 = nullptr, s2 = nullptr;
    static cudaEvent_t evFork = nullptr, evGemm = nullptr, evT = nullptr;
    static cudaEvent_t evG[NCHUNK];
    if (s1 == nullptr) {
        cudaStreamCreateWithFlags(&s1, cudaStreamNonBlocking);
        cudaStreamCreateWithFlags(&s2, cudaStreamNonBlocking);
        cudaEventCreateWithFlags(&evFork, cudaEventDisableTiming);
        cudaEventCreateWithFlags(&evGemm, cudaEventDisableTiming);
        cudaEventCreateWithFlags(&evT, cudaEventDisableTiming);
        for (int c = 0; c < NCHUNK; c++)
            cudaEventCreateWithFlags(&evG[c], cudaEventDisableTiming);
        const int GEMM_SMEM = (4096 + NB * 64) * 8;
        cudaFuncSetAttribute(gemm_kernel, cudaFuncAttributeMaxDynamicSharedMemorySize, GEMM_SMEM);
    }
    const int GEMM_SMEM = (4096 + NB * 64) * 8;

    // s0: init -> hist -> [fork] offsets -> bucket -> gathers (pipelined)
    // s1:                        gemm (needs cnt only)
    // s2:                        time chunks (each after its gather)
    init_kernel<<<(NN + 255) / 256, 256>>>();
    hist_kernel<<<(EE + 255) / 256, 256>>>(ei + EE);
    cudaEventRecord(evFork, 0);

    cudaStreamWaitEvent(s1, evFork, 0);
    gemm_kernel<<<(NN + NB - 1) / NB, 128, GEMM_SMEM, s1>>>(x, W);
    cudaEventRecord(evGemm, s1);

    offsets_kernel<<<(NN + 1023) / 1024, 1024>>>();
    bucket_kernel<<<(EE + 255) / 256, 256>>>(ei);

    cudaStreamWaitEvent(0, evGemm, 0);
    for (int c = 0; c < NCHUNK; c++) {
        gather_kernel<<<(CHUNK * 32 + 255) / 256, 256>>>(b, c * CHUNK);
        cudaEventRecord(evG[c], 0);
        cudaStreamWaitEvent(s2, evG[c], 0);
        time_kernel<<<(CHUNK * 4 + 255) / 256, 256, 0, s2>>>(o_out, z_out, c * CHUNK);
    }
    cudaEventRecord(evT, s2);
    cudaStreamWaitEvent(0, evT, 0);
}

// round 13
// speedup vs baseline: 1.1364x; 1.1364x over previous
#include <cuda_runtime.h>
#include <cstdint>

#define NN 100000
#define EE 1600000
#define IN_DIM 128
#define OUT_DIM 64
#define TT 8
#define EPS_ 1e-7f
#define CSR_CAP (EE + 4 * NN)
#define NB 48                     // nodes per GEMM block (4 warps x 12)
#define COSH1 1.5430806348152437f

typedef unsigned long long ull;

// ---------------- scratch ----------------
__device__ int   g_cnt[NN];
__device__ int   g_off[NN];
__device__ int   g_cur[NN];
__device__ int   g_csr[CSR_CAP];                       // padding slots = NN (dummy)
__device__ float g_hs[(size_t)(NN + 1) * OUT_DIM];     // dinv[n]*(x@W); row NN zeros
__device__ float g_h[(size_t)NN * OUT_DIM];            // aggregated + bias
__device__ int   g_cursor;

__device__ __forceinline__ void pfma(ull& acc, ull x, ull w) {
    asm("fma.rn.f32x2 %0, %1, %2, %0;" : "+l"(acc) : "l"(x), "l"(w));
}

// ---------------- kernels ----------------

__global__ void init_kernel() {
    int i = blockIdx.x * blockDim.x + threadIdx.x;
    if (i < NN) g_cnt[i] = 0;
    if (i < OUT_DIM) g_hs[(size_t)NN * OUT_DIM + i] = 0.0f;
    if (i == 0) g_cursor = 0;
}

__global__ void hist_kernel(const int* __restrict__ dst) {
    int e = blockIdx.x * blockDim.x + threadIdx.x;
    if (e >= EE) return;
    atomicAdd(&g_cnt[dst[e]], 1);
}

// per-block scan + global bump allocator; pads buckets to multiple of 4
__global__ void offsets_kernel() {
    int i = blockIdx.x * 1024 + threadIdx.x;
    int lane = threadIdx.x & 31, wid = threadIdx.x >> 5;
    int c = (i < NN) ? g_cnt[i] : 0;
    int pc = (c + 3) & ~3;

    int v = pc;
#pragma unroll
    for (int o = 1; o < 32; o <<= 1) {
        int t = __shfl_up_sync(0xffffffffu, v, o);
        if (lane >= o) v += t;
    }
    __shared__ int wsum[32];
    __shared__ int base;
    if (lane == 31) wsum[wid] = v;
    __syncthreads();
    if (wid == 0) {
        int w = wsum[lane];
#pragma unroll
        for (int o = 1; o < 32; o <<= 1) {
            int t = __shfl_up_sync(0xffffffffu, w, o);
            if (lane >= o) w += t;
        }
        wsum[lane] = w;
    }
    __syncthreads();
    int incl = v + ((wid > 0) ? wsum[wid - 1] : 0);
    if (threadIdx.x == 1023) base = atomicAdd(&g_cursor, incl);
    __syncthreads();
    if (i < NN) {
        int off = base + incl - pc;
        g_off[i] = off;
        g_cur[i] = off;
        for (int j = c; j < pc; j++) g_csr[off + j] = NN;   // dummy padding
    }
}

// h_s = dinv * (x @ W): 12 nodes per warp, 4 warps/block (NB=48); dinv inline
__global__ void __launch_bounds__(128) gemm_kernel(const float* __restrict__ x,
                                                   const float* __restrict__ W) {
    extern __shared__ ull sm[];
    ull* Wq = sm;            // [32 kk2][64 j][2] pairs-of-pairs, 32 KB
    ull* xs = sm + 4096;     // [48 node][64 kk], 24 KB

    int tid = threadIdx.x;
    int n0 = blockIdx.x * NB;

    for (int i = tid; i < 64 * 64; i += 128) {
        int kk = i >> 6, j = i & 63;
        int kk2 = kk >> 1, lo = kk & 1;
        float w0 = W[(2 * kk) * OUT_DIM + j];
        float w1 = W[(2 * kk + 1) * OUT_DIM + j];
        ull p; asm("mov.b64 %0, {%1, %2};" : "=l"(p) : "f"(w0), "f"(w1));
        Wq[kk2 * 128 + j * 2 + lo] = p;
    }
    const ull* x2 = (const ull*)x;
    for (int i = tid; i < NB * 64; i += 128) {
        int node = i >> 6, kk = i & 63;
        int gn = n0 + node;
        xs[i] = (gn < NN) ? x2[(size_t)gn * 64 + kk] : 0ull;
    }
    __syncthreads();

    int wid = tid >> 5, lane = tid & 31;
    const ull* xw = xs + wid * 12 * 64;

    ull a0[12], a1[12];
#pragma unroll
    for (int n = 0; n < 12; n++) { a0[n] = 0ull; a1[n] = 0ull; }

#pragma unroll 2
    for (int kk2 = 0; kk2 < 32; kk2++) {
        ulonglong2 wa = *(const ulonglong2*)(Wq + kk2 * 128 + 2 * lane);
        ulonglong2 wb = *(const ulonglong2*)(Wq + kk2 * 128 + 2 * (lane + 32));
#pragma unroll
        for (int n = 0; n < 12; n++) {
            ulonglong2 xv = *(const ulonglong2*)(xw + n * 64 + 2 * kk2);
            pfma(a0[n], xv.x, wa.x);
            pfma(a1[n], xv.x, wb.x);
            pfma(a0[n], xv.y, wa.y);
            pfma(a1[n], xv.y, wb.y);
        }
    }

#pragma unroll
    for (int n = 0; n < 12; n++) {
        int gn = n0 + wid * 12 + n;
        if (gn >= NN) break;
        float lo, hi, lo1, hi1;
        asm("mov.b64 {%0, %1}, %2;" : "=f"(lo), "=f"(hi) : "l"(a0[n]));
        asm("mov.b64 {%0, %1}, %2;" : "=f"(lo1), "=f"(hi1) : "l"(a1[n]));
        float di = rsqrtf((float)(g_cnt[gn] + 1));
        g_hs[(size_t)gn * OUT_DIM + lane]      = (lo + hi) * di;
        g_hs[(size_t)gn * OUT_DIM + lane + 32] = (lo1 + hi1) * di;
    }
}

__global__ void bucket_kernel(const int* __restrict__ ei) {
    int e = blockIdx.x * blockDim.x + threadIdx.x;
    if (e >= EE) return;
    int s = ei[e];
    int d = ei[EE + e];
    int pos = atomicAdd(&g_cur[d], 1);
    g_csr[pos] = s;
}

// warp per node: gather in-edges (pad-4 buckets, 2 groups in flight)
__global__ void gather_kernel(const float* __restrict__ b) {
    int warp = (blockIdx.x * blockDim.x + threadIdx.x) >> 5;
    int lane = threadIdx.x & 31;
    if (warp >= NN) return;
    const int n = warp;

    int cnt = g_cnt[n];
    int off = g_off[n];
    int mp = (cnt + 3) & ~3;
    const float2* hs2 = (const float2*)g_hs;

    float2 acc = hs2[(size_t)n * 32 + lane];   // self loop (prescaled by dinv[n])

#pragma unroll 2
    for (int i = 0; i < mp; i += 4) {
        int4 a = __ldg((const int4*)(g_csr + off + i));
        float2 v0 = hs2[(size_t)a.x * 32 + lane];
        float2 v1 = hs2[(size_t)a.y * 32 + lane];
        float2 v2 = hs2[(size_t)a.z * 32 + lane];
        float2 v3 = hs2[(size_t)a.w * 32 + lane];
        acc.x += (v0.x + v1.x) + (v2.x + v3.x);
        acc.y += (v0.y + v1.y) + (v2.y + v3.y);
    }

    float di = rsqrtf((float)(cnt + 1));
    float2 bb = ((const float2*)b)[lane];
    float2 out = make_float2(fmaf(di, acc.x, bb.x), fmaf(di, acc.y, bb.y));
    ((float2*)g_h)[(size_t)n * 32 + lane] = out;
}

// quad per node (4 lanes, 16 comps each): 8-step Lorentz recurrence
__global__ void __launch_bounds__(256) time_kernel(float* __restrict__ o_out,
                                                   float* __restrict__ z_out) {
    int gid = blockIdx.x * 256 + threadIdx.x;
    int node = gid >> 2;
    if (node >= NN) return;
    int q = gid & 3;

    const float4* hp = (const float4*)(g_h + (size_t)node * OUT_DIM + q * 16);
    float4 h[4], z[4], u[4];
#pragma unroll
    for (int j = 0; j < 4; j++) h[j] = hp[j];
#pragma unroll
    for (int j = 0; j < 4; j++) z[j] = make_float4(0.f, 0.f, 0.f, 0.f);
    if (q == 0) z[0].x = 1.0f;

#pragma unroll
    for (int t = 0; t < TT; t++) {
        float p = 0.f;
#pragma unroll
        for (int j = 0; j < 4; j++) {
            p = fmaf(z[j].x, h[j].x, p); p = fmaf(z[j].y, h[j].y, p);
            p = fmaf(z[j].z, h[j].z, p); p = fmaf(z[j].w, h[j].w, p);
        }
        p += __shfl_xor_sync(0xffffffffu, p, 1);
        p += __shfl_xor_sync(0xffffffffu, p, 2);
        float t00 = __shfl_sync(0xffffffffu, z[0].x * h[0].x, 0, 4);
        float lz = p - 2.0f * t00;

#pragma unroll
        for (int j = 0; j < 4; j++) {
            u[j].x = fmaf(lz, z[j].x, h[j].x);
            u[j].y = fmaf(lz, z[j].y, h[j].y);
            u[j].z = fmaf(lz, z[j].z, h[j].z);
            u[j].w = fmaf(lz, z[j].w, h[j].w);
        }
        float qq = 0.f;
#pragma unroll
        for (int j = 0; j < 4; j++) {
            qq = fmaf(u[j].x, u[j].x, qq); qq = fmaf(u[j].y, u[j].y, qq);
            qq = fmaf(u[j].z, u[j].z, qq); qq = fmaf(u[j].w, u[j].w, qq);
        }
        qq += __shfl_xor_sync(0xffffffffu, qq, 1);
        qq += __shfl_xor_sync(0xffffffffu, qq, 2);
        float u0 = __shfl_sync(0xffffffffu, u[0].x, 0, 4);
        float uu = qq - 2.0f * u0 * u0;

        float un2 = fmaxf(uu, EPS_);
        float un = sqrtf(un2);
        float ch, sh_;
        if (un < 0.03f) {                       // series (avoids cancellation)
            ch = fmaf(un2, 0.5f, 1.0f);
            sh_ = fmaf(un2, 0.16666667f, 1.0f);
        } else {
            float e = __expf(un);
            float ei = __fdividef(1.0f, e);
            ch = 0.5f * (e + ei);
            sh_ = __fdividef(0.5f * (e - ei), un);
        }
#pragma unroll
        for (int j = 0; j < 4; j++) {
            z[j].x = fmaf(ch, z[j].x, sh_ * u[j].x);
            z[j].y = fmaf(ch, z[j].y, sh_ * u[j].y);
            z[j].z = fmaf(ch, z[j].z, sh_ * u[j].z);
            z[j].w = fmaf(ch, z[j].w, sh_ * u[j].w);
        }

        // spike: arccosh(z0) >= 1  <=>  z0 >= cosh(1)
        float z0b = __shfl_sync(0xffffffffu, z[0].x, 0, 4);
        bool spike = (z0b >= COSH1);
        if (spike) {
#pragma unroll
            for (int j = 0; j < 4; j++) z[j] = make_float4(0.f, 0.f, 0.f, 0.f);
            if (q == 0) z[0].x = 1.0f;
        }

        if (q == 0) {
            float ov = spike ? 1.0f : 0.0f;
            __stcs(o_out + (size_t)t * NN + node, ov);
        }
        float* zp = z_out + (size_t)t * NN * OUT_DIM + (size_t)node * OUT_DIM + q * 16;
#pragma unroll
        for (int j = 0; j < 4; j++) __stcs((float4*)(zp + 4 * j), z[j]);
    }
}

// ---------------- launch ----------------
extern "C" void kernel_launch(void* const* d_in, const int* in_sizes, int n_in,
                              void* d_out, int out_size) {
    const float* x  = (const float*)d_in[0];
    const int*   ei = (const int*)d_in[1];
    const float* W  = (const float*)d_in[2];
    const float* b  = (const float*)d_in[3];

    float* o_out = (float*)d_out;              // [T, N]
    float* z_out = o_out + (size_t)TT * NN;    // [T, N, 64]

    static cudaStream_t s1 = nullptr;
    static cudaEvent_t evFork = nullptr, evJoin = nullptr;
    if (s1 == nullptr) {
        cudaStreamCreateWithFlags(&s1, cudaStreamNonBlocking);
        cudaEventCreateWithFlags(&evFork, cudaEventDisableTiming);
        cudaEventCreateWithFlags(&evJoin, cudaEventDisableTiming);
        const int GEMM_SMEM = (4096 + NB * 64) * 8;
        cudaFuncSetAttribute(gemm_kernel, cudaFuncAttributeMaxDynamicSharedMemorySize, GEMM_SMEM);
    }
    const int GEMM_SMEM = (4096 + NB * 64) * 8;

    // s0: init -> hist -> [fork] offsets -> bucket -> [join] gather -> time
    // s1:                        gemm (reads cnt only)
    init_kernel<<<(NN + 255) / 256, 256>>>();
    hist_kernel<<<(EE + 255) / 256, 256>>>(ei + EE);
    cudaEventRecord(evFork, 0);

    cudaStreamWaitEvent(s1, evFork, 0);
    gemm_kernel<<<(NN + NB - 1) / NB, 128, GEMM_SMEM, s1>>>(x, W);
    cudaEventRecord(evJoin, s1);

    offsets_kernel<<<(NN + 1023) / 1024, 1024>>>();
    bucket_kernel<<<(EE + 255) / 256, 256>>>(ei);

    cudaStreamWaitEvent(0, evJoin, 0);
    gather_kernel<<<(NN * 32 + 255) / 256, 256>>>(b);
    time_kernel<<<(NN * 4 + 255) / 256, 256>>>(o_out, z_out);
}